// round 16
// baseline (speedup 1.0000x reference)
#include <cuda_runtime.h>
#include <cuda_bf16.h>
#include <cstdint>

// ---------------------------------------------------------------------------
// Two-level counting sort with FUSED fine-sort + gather.
//   P1: coarse-bin edges into 1024-vertex buckets (smem staging, coalesced
//       global writes, ~1 global atomic per bucket per block).
//   P2F: persistent blocks, one bucket at a time: smem hist/scan/place, then
//        gather x rows via smem indices and write the mean directly.
//        (g_perm / g_offsets never touch global memory.)
//   P3: exact fixup for bucket-capacity overflow (normally empty).
// ---------------------------------------------------------------------------
#define VB_SHIFT   10
#define VB         1024                 // vertices per coarse bucket
#define NBUCK_MAX  2048                 // supports V <= 2M
#define CAP_B      8192                 // binned-edge capacity per bucket
#define EPB        4096                 // edges per P1 block
#define P1_THREADS 512
#define OVER_MAX   (1 << 20)

__device__ int2 g_bucket[(size_t)NBUCK_MAX * CAP_B];  // coarse bins (e, v)
__device__ int  g_bucket_cnt[NBUCK_MAX];              // edges per bucket
__device__ int  g_deg[2u << 20];                      // true degree per vertex
__device__ int  g_ovcnt[2u << 20];                    // per-vertex overflow
__device__ int  g_over_n;
__device__ int2 g_over[OVER_MAX];                     // overflow (e, v)

// ---------------------------------------------------------------------------
// P1: coarse binning. Per 4096-edge block: smem histogram over buckets,
// 2-level shuffle scan, one global atomic reservation per touched bucket,
// smem staging, coalesced flush of (e, v) pairs.
// ---------------------------------------------------------------------------
__global__ void __launch_bounds__(P1_THREADS)
p1_bin_kernel(const int* __restrict__ ids, int n, int nbuck)
{
    __shared__ int  s_cnt[NBUCK_MAX];
    __shared__ int  s_off[NBUCK_MAX];   // EXCLUSIVE offsets within block
    __shared__ int  s_base[NBUCK_MAX];  // global reservation base
    __shared__ int  s_fill[NBUCK_MAX];
    __shared__ int  s_wsum[32];
    __shared__ int2 s_stage[EPB];       // 32 KB

    int t = threadIdx.x;
    int lane = t & 31, wid = t >> 5;
    int start = blockIdx.x * EPB;
    int cnt_this = n - start; if (cnt_this > EPB) cnt_this = EPB;

    for (int i = t; i < nbuck; i += P1_THREADS) { s_cnt[i] = 0; s_fill[i] = 0; }
    __syncthreads();

    // Load 8 ids per thread (2 x int4 when fully in range) + smem histogram.
    int myv[8];
    int ebase = start + t * 8;
    if (ebase + 8 <= n) {
        int4 a = __ldg((const int4*)(ids + ebase));
        int4 b = __ldg((const int4*)(ids + ebase + 4));
        myv[0] = a.x; myv[1] = a.y; myv[2] = a.z; myv[3] = a.w;
        myv[4] = b.x; myv[5] = b.y; myv[6] = b.z; myv[7] = b.w;
    } else {
        #pragma unroll
        for (int k = 0; k < 8; k++)
            myv[k] = (ebase + k < n) ? __ldg(ids + ebase + k) : -1;
    }
    #pragma unroll
    for (int k = 0; k < 8; k++)
        if (myv[k] >= 0) atomicAdd(&s_cnt[myv[k] >> VB_SHIFT], 1);
    __syncthreads();

    // Exclusive scan of s_cnt (nbuck <= 2048), 4 entries per thread.
    {
        int i0 = t * 4;
        int c0 = (i0     < nbuck) ? s_cnt[i0]     : 0;
        int c1 = (i0 + 1 < nbuck) ? s_cnt[i0 + 1] : 0;
        int c2 = (i0 + 2 < nbuck) ? s_cnt[i0 + 2] : 0;
        int c3 = (i0 + 3 < nbuck) ? s_cnt[i0 + 3] : 0;
        int ts = c0 + c1 + c2 + c3;
        int incl = ts;
        #pragma unroll
        for (int d = 1; d < 32; d <<= 1) {
            int u = __shfl_up_sync(0xffffffffu, incl, d);
            if (lane >= d) incl += u;
        }
        if (lane == 31) s_wsum[wid] = incl;
        __syncthreads();
        if (wid == 0) {
            int w = (lane < P1_THREADS / 32) ? s_wsum[lane] : 0;
            int ws = w;
            #pragma unroll
            for (int d = 1; d < 32; d <<= 1) {
                int u = __shfl_up_sync(0xffffffffu, ws, d);
                if (lane >= d) ws += u;
            }
            s_wsum[lane] = ws - w;
        }
        __syncthreads();
        int excl = incl - ts + s_wsum[wid];
        if (i0     < nbuck) s_off[i0]     = excl;
        if (i0 + 1 < nbuck) s_off[i0 + 1] = excl + c0;
        if (i0 + 2 < nbuck) s_off[i0 + 2] = excl + c0 + c1;
        if (i0 + 3 < nbuck) s_off[i0 + 3] = excl + c0 + c1 + c2;
    }
    __syncthreads();

    // Global reservation (one atomic per touched bucket).
    for (int i = t; i < nbuck; i += P1_THREADS) {
        int c = s_cnt[i];
        s_base[i] = (c > 0) ? atomicAdd(&g_bucket_cnt[i], c) : 0;
    }
    __syncthreads();

    // Stage into smem grouped by bucket.
    #pragma unroll
    for (int k = 0; k < 8; k++) {
        int v = myv[k];
        if (v >= 0) {
            int b = v >> VB_SHIFT;
            int r = atomicAdd(&s_fill[b], 1);
            s_stage[s_off[b] + r] = make_int2(ebase + k, v);
        }
    }
    __syncthreads();

    // Coalesced flush.
    for (int i = t; i < cnt_this; i += P1_THREADS) {
        int2 ent = s_stage[i];
        int b = ent.y >> VB_SHIFT;
        int gpos = s_base[b] + (i - s_off[b]);
        if (gpos < CAP_B) {
            g_bucket[(size_t)b * CAP_B + gpos] = ent;
        } else {                                    // exact overflow path
            int o = atomicAdd(&g_over_n, 1);
            if (o < OVER_MAX) g_over[o] = ent;
            atomicAdd(&g_ovcnt[ent.y], 1);
        }
    }
}

// ---------------------------------------------------------------------------
// P2F: fused fine-sort + gather. Persistent blocks grid-stride over buckets.
// Per bucket: smem histogram over 1024 local vertices (1 per thread), smem
// scan, smem placement into s_perm, then gather: 8 threads per vertex,
// thread s covers feature quad s; edge indices come from smem (no global
// perm traffic at all). Output mean written directly; true degree (incl.
// overflow) recorded in g_deg for the fixup path.
// Dynamic smem: s_off[VB+1] | s_fill[VB] | s_perm[CAP_B]  (~41 KB).
// ---------------------------------------------------------------------------
__global__ void __launch_bounds__(1024, 2)
p2_fused_kernel(const float4* __restrict__ x4, float4* __restrict__ out4,
                int V, int nbuck)
{
    extern __shared__ int sm[];
    int* s_off  = sm;              // VB+1 entries
    int* s_fill = sm + VB + 1;     // VB entries (hist, then fill counters)
    int* s_perm = sm + 2 * VB + 1; // CAP_B entries
    __shared__ int s_wsum[32];

    int t = threadIdx.x;
    int lane = t & 31, wid = t >> 5;

    for (int b = blockIdx.x; b < nbuck; b += gridDim.x) {
        int vbase = b << VB_SHIFT;
        int nv = V - vbase; if (nv > VB) nv = VB;
        int m = g_bucket_cnt[b]; if (m > CAP_B) m = CAP_B;
        const int2* bk = g_bucket + (size_t)b * CAP_B;

        // --- histogram over local vertices (1 counter per thread) ---
        s_fill[t] = 0;
        __syncthreads();
        for (int i = t; i < m; i += 1024) {
            int2 e = __ldg(&bk[i]);
            atomicAdd(&s_fill[e.y - vbase], 1);
        }
        __syncthreads();

        // --- exclusive scan of 1024 counters (1 per thread) ---
        int c = s_fill[t];
        int incl = c;
        #pragma unroll
        for (int d = 1; d < 32; d <<= 1) {
            int u = __shfl_up_sync(0xffffffffu, incl, d);
            if (lane >= d) incl += u;
        }
        if (lane == 31) s_wsum[wid] = incl;
        __syncthreads();
        if (wid == 0) {
            int w = s_wsum[lane];
            int ws = w;
            #pragma unroll
            for (int d = 1; d < 32; d <<= 1) {
                int u = __shfl_up_sync(0xffffffffu, ws, d);
                if (lane >= d) ws += u;
            }
            s_wsum[lane] = ws - w;
        }
        __syncthreads();
        int excl = incl - c + s_wsum[wid];
        s_off[t] = excl;
        if (t == 1023) s_off[VB] = excl + c;
        s_fill[t] = 0;                     // reset as fill counters
        __syncthreads();

        // --- placement into smem perm ---
        for (int i = t; i < m; i += 1024) {
            int2 e = __ldg(&bk[i]);
            int vl = e.y - vbase;
            int r = atomicAdd(&s_fill[vl], 1);
            s_perm[s_off[vl] + r] = e.x;
        }
        __syncthreads();

        // --- gather + mean: 8 threads per local vertex ---
        for (int slot = t; slot < nv * 8; slot += 1024) {
            int vl = slot >> 3;
            int s  = slot & 7;
            int beg = s_off[vl];
            int end = s_off[vl + 1];
            int vglob = vbase + vl;
            int ov = __ldg(&g_ovcnt[vglob]);
            int deg = (end - beg) + ov;

            float4 acc = make_float4(0.f, 0.f, 0.f, 0.f);
            for (int base = beg; base < end; base += 8) {
                int e[8];
                #pragma unroll
                for (int u = 0; u < 8; u++) {
                    int j = base + u;
                    e[u] = (j < end) ? s_perm[j] : -1;
                }
                #pragma unroll
                for (int u = 0; u < 8; u++) {
                    if (e[u] >= 0) {
                        float4 a = __ldg(x4 + (long long)e[u] * 8 + s);
                        acc.x += a.x; acc.y += a.y; acc.z += a.z; acc.w += a.w;
                    }
                }
            }

            float inv = 1.0f / fmaxf((float)deg, 1.0f);
            out4[(long long)vglob * 8 + s] =
                make_float4(acc.x * inv, acc.y * inv, acc.z * inv, acc.w * inv);
            if (s == 0) g_deg[vglob] = deg;      // for the fixup path
        }
        __syncthreads();                          // protect smem reuse
    }
}

// ---------------------------------------------------------------------------
// P3: exact overflow fixup (normally zero entries).
// ---------------------------------------------------------------------------
__global__ void fixup_kernel(const float4* __restrict__ x4,
                             float* __restrict__ out)
{
    int cnt = g_over_n;
    if (cnt > OVER_MAX) cnt = OVER_MAX;
    int stride = gridDim.x * blockDim.x;
    for (int i = blockIdx.x * blockDim.x + threadIdx.x; i < cnt; i += stride) {
        int2 ent = g_over[i];
        int e = ent.x, v = ent.y;
        float inv = 1.0f / fmaxf((float)g_deg[v], 1.0f);
        float* dst = out + (long long)v * 32;
        #pragma unroll
        for (int s = 0; s < 8; s++) {
            float4 a = __ldg(x4 + (long long)e * 8 + s);
            asm volatile("red.global.add.v4.f32 [%0], {%1, %2, %3, %4};"
                         :: "l"(dst + s * 4),
                            "f"(a.x * inv), "f"(a.y * inv),
                            "f"(a.z * inv), "f"(a.w * inv)
                         : "memory");
        }
    }
}

extern "C" void kernel_launch(void* const* d_in, const int* in_sizes, int n_in,
                              void* d_out, int out_size)
{
    const float4* x4  = (const float4*)d_in[0];
    const int*    ids = (const int*)d_in[1];

    int n_he = in_sizes[1];                     // element count of vertex_ids
    int V    = (int)((long long)out_size / 32); // output is [V, 32]
    int nbuck = (V + VB - 1) >> VB_SHIFT;
    if (nbuck > NBUCK_MAX) nbuck = NBUCK_MAX;   // (bench shape: V=1M -> 977)

    // Zero bucket counts, overflow counts, overflow length.
    void* p = nullptr;
    cudaGetSymbolAddress(&p, g_bucket_cnt);
    cudaMemsetAsync(p, 0, (size_t)nbuck * sizeof(int));
    cudaGetSymbolAddress(&p, g_ovcnt);
    cudaMemsetAsync(p, 0, (size_t)V * sizeof(int));
    cudaGetSymbolAddress(&p, g_over_n);
    cudaMemsetAsync(p, 0, sizeof(int));

    // P1: coarse binning.
    p1_bin_kernel<<<(n_he + EPB - 1) / EPB, P1_THREADS>>>(ids, n_he, nbuck);

    // P2F: fused fine-sort + gather (persistent, 2 CTAs/SM).
    size_t smem = (size_t)(2 * VB + 1 + CAP_B) * sizeof(int);
    cudaFuncSetAttribute(p2_fused_kernel,
                         cudaFuncAttributeMaxDynamicSharedMemorySize, (int)smem);
    int pblocks = 2 * 148;
    if (pblocks > nbuck) pblocks = nbuck;
    p2_fused_kernel<<<pblocks, 1024, smem>>>(x4, (float4*)d_out, V, nbuck);

    // P3: exact overflow fixup (tiny; normally exits immediately).
    fixup_kernel<<<32, 256>>>(x4, (float*)d_out);
}

// round 17
// speedup vs baseline: 1.0171x; 1.0171x over previous
#include <cuda_runtime.h>
#include <cuda_bf16.h>
#include <cstdint>

// ---------------------------------------------------------------------------
// Two-level counting sort + gather (split kernels — fusion measured worse).
//   P1: coarse-bin edges into 1024-vertex buckets (smem staging, coalesced
//       global writes, ~1 global atomic per bucket per block).
//   P2: per-bucket fine sort; bucket read ONCE into smem, ranks captured
//       from the hist atomics -> placement with zero atomics.
//   P3: gather + mean (measured-best inner loop, barrier-free).
//   P4: exact fixup for bucket-capacity overflow (normally empty).
// ---------------------------------------------------------------------------
#define VB_SHIFT   10
#define VB         1024                 // vertices per coarse bucket
#define NBUCK_MAX  2048                 // supports V <= 2M
#define CAP_B      8192                 // binned-edge capacity per bucket
#define EPB        4096                 // edges per P1 block
#define P1_THREADS 512
#define OVER_MAX   (1 << 20)

__device__ int2 g_bucket[(size_t)NBUCK_MAX * CAP_B];  // coarse bins (e, v)
__device__ int  g_bucket_cnt[NBUCK_MAX];              // edges per bucket
__device__ int  g_offsets[2u << 20];                  // global inclusive ends
__device__ int  g_perm[8u << 20];                     // dense sorted edge ids
__device__ int  g_ovcnt[2u << 20];                    // per-vertex overflow
__device__ int  g_over_n;
__device__ int2 g_over[OVER_MAX];                     // overflow (e, v)

// ---------------------------------------------------------------------------
// P1: coarse binning (measured-good form). Per 4096-edge block: smem
// histogram over buckets, shuffle scan, one global atomic reservation per
// touched bucket, smem staging, coalesced flush of (e, v) pairs.
// ---------------------------------------------------------------------------
__global__ void __launch_bounds__(P1_THREADS)
p1_bin_kernel(const int* __restrict__ ids, int n, int nbuck)
{
    __shared__ int  s_cnt[NBUCK_MAX];
    __shared__ int  s_off[NBUCK_MAX];   // EXCLUSIVE offsets within block
    __shared__ int  s_base[NBUCK_MAX];  // global reservation base
    __shared__ int  s_fill[NBUCK_MAX];
    __shared__ int  s_wsum[32];
    __shared__ int2 s_stage[EPB];       // 32 KB

    int t = threadIdx.x;
    int lane = t & 31, wid = t >> 5;
    int start = blockIdx.x * EPB;
    int cnt_this = n - start; if (cnt_this > EPB) cnt_this = EPB;

    for (int i = t; i < nbuck; i += P1_THREADS) { s_cnt[i] = 0; s_fill[i] = 0; }
    __syncthreads();

    // Load 8 ids per thread (2 x int4 when fully in range) + smem histogram.
    int myv[8];
    int ebase = start + t * 8;
    if (ebase + 8 <= n) {
        int4 a = __ldg((const int4*)(ids + ebase));
        int4 b = __ldg((const int4*)(ids + ebase + 4));
        myv[0] = a.x; myv[1] = a.y; myv[2] = a.z; myv[3] = a.w;
        myv[4] = b.x; myv[5] = b.y; myv[6] = b.z; myv[7] = b.w;
    } else {
        #pragma unroll
        for (int k = 0; k < 8; k++)
            myv[k] = (ebase + k < n) ? __ldg(ids + ebase + k) : -1;
    }
    #pragma unroll
    for (int k = 0; k < 8; k++)
        if (myv[k] >= 0) atomicAdd(&s_cnt[myv[k] >> VB_SHIFT], 1);
    __syncthreads();

    // Exclusive scan of s_cnt (nbuck <= 2048), 4 entries per thread.
    {
        int i0 = t * 4;
        int c0 = (i0     < nbuck) ? s_cnt[i0]     : 0;
        int c1 = (i0 + 1 < nbuck) ? s_cnt[i0 + 1] : 0;
        int c2 = (i0 + 2 < nbuck) ? s_cnt[i0 + 2] : 0;
        int c3 = (i0 + 3 < nbuck) ? s_cnt[i0 + 3] : 0;
        int ts = c0 + c1 + c2 + c3;
        int incl = ts;
        #pragma unroll
        for (int d = 1; d < 32; d <<= 1) {
            int u = __shfl_up_sync(0xffffffffu, incl, d);
            if (lane >= d) incl += u;
        }
        if (lane == 31) s_wsum[wid] = incl;
        __syncthreads();
        if (wid == 0) {
            int w = (lane < P1_THREADS / 32) ? s_wsum[lane] : 0;
            int ws = w;
            #pragma unroll
            for (int d = 1; d < 32; d <<= 1) {
                int u = __shfl_up_sync(0xffffffffu, ws, d);
                if (lane >= d) ws += u;
            }
            s_wsum[lane] = ws - w;
        }
        __syncthreads();
        int excl = incl - ts + s_wsum[wid];
        if (i0     < nbuck) s_off[i0]     = excl;
        if (i0 + 1 < nbuck) s_off[i0 + 1] = excl + c0;
        if (i0 + 2 < nbuck) s_off[i0 + 2] = excl + c0 + c1;
        if (i0 + 3 < nbuck) s_off[i0 + 3] = excl + c0 + c1 + c2;
    }
    __syncthreads();

    // Global reservation (one atomic per touched bucket).
    for (int i = t; i < nbuck; i += P1_THREADS) {
        int c = s_cnt[i];
        s_base[i] = (c > 0) ? atomicAdd(&g_bucket_cnt[i], c) : 0;
    }
    __syncthreads();

    // Stage into smem grouped by bucket.
    #pragma unroll
    for (int k = 0; k < 8; k++) {
        int v = myv[k];
        if (v >= 0) {
            int b = v >> VB_SHIFT;
            int r = atomicAdd(&s_fill[b], 1);
            s_stage[s_off[b] + r] = make_int2(ebase + k, v);
        }
    }
    __syncthreads();

    // Coalesced flush.
    for (int i = t; i < cnt_this; i += P1_THREADS) {
        int2 ent = s_stage[i];
        int b = ent.y >> VB_SHIFT;
        int gpos = s_base[b] + (i - s_off[b]);
        if (gpos < CAP_B) {
            g_bucket[(size_t)b * CAP_B + gpos] = ent;
        } else {                                    // exact overflow path
            int o = atomicAdd(&g_over_n, 1);
            if (o < OVER_MAX) g_over[o] = ent;
            atomicAdd(&g_ovcnt[ent.y], 1);
        }
    }
}

// ---------------------------------------------------------------------------
// P2: per-bucket fine sort. One block per bucket. Bucket entries are read
// from global ONCE: the hist pass stages (e, vlocal<<16|rank) in smem, with
// rank coming from the hist atomic's return value -> the placement pass is
// smem-only and ATOMIC-FREE.
// Dynamic smem: s_cnt[VB] | s_off[VB+1] | s_stage[CAP_B](int2) | s_perm[CAP_B]
//   = 4 + 4 + 64 + 32 KB ~= 104 KB -> 2 CTAs/SM.
// ---------------------------------------------------------------------------
__global__ void __launch_bounds__(1024, 2)
p2_sort_kernel(int V, int nbuck)
{
    extern __shared__ int sm[];
    int*  s_cnt   = sm;                        // VB
    int*  s_off   = sm + VB;                   // VB+1
    int2* s_stage = (int2*)(sm + 2 * VB + 2);  // CAP_B int2 (8B-aligned)
    int*  s_perm  = sm + 2 * VB + 2 + 2 * CAP_B;
    __shared__ int s_wsum[32];
    __shared__ int s_base_sh;

    int b = blockIdx.x;
    int t = threadIdx.x;
    int lane = t & 31, wid = t >> 5;
    int vbase = b << VB_SHIFT;
    int nv = V - vbase; if (nv > VB) nv = VB;

    int m = g_bucket_cnt[b]; if (m > CAP_B) m = CAP_B;

    // global base = sum_{j<b} min(cnt[j], CAP_B)
    {
        int partial = 0;
        for (int j = t; j < b; j += 1024) {
            int c = g_bucket_cnt[j]; if (c > CAP_B) c = CAP_B;
            partial += c;
        }
        #pragma unroll
        for (int d = 16; d > 0; d >>= 1)
            partial += __shfl_down_sync(0xffffffffu, partial, d);
        if (lane == 0) s_wsum[wid] = partial;
        __syncthreads();
        if (t < 32) {
            int x = s_wsum[t];
            #pragma unroll
            for (int d = 16; d > 0; d >>= 1)
                x += __shfl_down_sync(0xffffffffu, x, d);
            if (t == 0) s_base_sh = x;
        }
        __syncthreads();
    }
    int base = s_base_sh;

    const int2* bk = g_bucket + (size_t)b * CAP_B;

    // --- single global read: histogram + rank capture + smem staging ---
    s_cnt[t] = 0;
    __syncthreads();
    for (int i = t; i < m; i += 1024) {
        int2 e = __ldg(&bk[i]);
        int vl = e.y - vbase;
        int r = atomicAdd(&s_cnt[vl], 1);
        s_stage[i] = make_int2(e.x, (vl << 16) | r);
    }
    __syncthreads();

    // --- exclusive scan of 1024 counters (1 per thread) ---
    int c = s_cnt[t];
    int incl = c;
    #pragma unroll
    for (int d = 1; d < 32; d <<= 1) {
        int u = __shfl_up_sync(0xffffffffu, incl, d);
        if (lane >= d) incl += u;
    }
    if (lane == 31) s_wsum[wid] = incl;
    __syncthreads();
    if (wid == 0) {
        int w = s_wsum[lane];
        int ws = w;
        #pragma unroll
        for (int d = 1; d < 32; d <<= 1) {
            int u = __shfl_up_sync(0xffffffffu, ws, d);
            if (lane >= d) ws += u;
        }
        s_wsum[lane] = ws - w;
    }
    __syncthreads();
    int excl = incl - c + s_wsum[wid];
    s_off[t] = excl;
    if (t == 1023) s_off[VB] = excl + c;
    __syncthreads();

    // --- atomic-free placement (smem -> smem) ---
    for (int i = t; i < m; i += 1024) {
        int2 ent = s_stage[i];
        int vl = ent.y >> 16;
        int r  = ent.y & 0xFFFF;
        s_perm[s_off[vl] + r] = ent.x;
    }
    __syncthreads();

    // --- publish global inclusive ends + coalesced perm flush ---
    for (int i = t; i < nv; i += 1024)
        g_offsets[vbase + i] = base + s_off[i + 1];
    for (int i = t; i < m; i += 1024)
        g_perm[base + i] = s_perm[i];
}

// ---------------------------------------------------------------------------
// P3: gather + mean (measured-best inner structure). 8 threads per vertex;
// thread s covers feature quad s as one float4.
// ---------------------------------------------------------------------------
__global__ void gather_kernel(const float4* __restrict__ x4,
                              float4* __restrict__ out4, int V)
{
    long long t = (long long)blockIdx.x * blockDim.x + threadIdx.x;
    int v = (int)(t >> 3);
    int s = (int)(t & 7);
    if (v >= V) return;

    int beg = (v == 0) ? 0 : __ldg(&g_offsets[v - 1]);
    int end = __ldg(&g_offsets[v]);
    int deg = (end - beg) + __ldg(&g_ovcnt[v]);

    float4 acc = make_float4(0.f, 0.f, 0.f, 0.f);

    for (int base = beg; base < end; base += 8) {
        int e[8];
        #pragma unroll
        for (int u = 0; u < 8; u++) {
            int j = base + u;
            e[u] = (j < end) ? __ldg(&g_perm[j]) : -1;
        }
        #pragma unroll
        for (int u = 0; u < 8; u++) {
            if (e[u] >= 0) {
                float4 a = __ldg(x4 + (long long)e[u] * 8 + s);
                acc.x += a.x; acc.y += a.y; acc.z += a.z; acc.w += a.w;
            }
        }
    }

    float inv = 1.0f / fmaxf((float)deg, 1.0f);
    out4[(long long)v * 8 + s] =
        make_float4(acc.x * inv, acc.y * inv, acc.z * inv, acc.w * inv);
}

// ---------------------------------------------------------------------------
// P4: exact overflow fixup (normally zero entries).
// ---------------------------------------------------------------------------
__global__ void fixup_kernel(const float4* __restrict__ x4,
                             float* __restrict__ out)
{
    int cnt = g_over_n;
    if (cnt > OVER_MAX) cnt = OVER_MAX;
    int stride = gridDim.x * blockDim.x;
    for (int i = blockIdx.x * blockDim.x + threadIdx.x; i < cnt; i += stride) {
        int2 ent = g_over[i];
        int e = ent.x, v = ent.y;
        int beg = (v == 0) ? 0 : g_offsets[v - 1];
        int end = g_offsets[v];
        float inv = 1.0f / fmaxf((float)(end - beg + g_ovcnt[v]), 1.0f);
        float* dst = out + (long long)v * 32;
        #pragma unroll
        for (int s = 0; s < 8; s++) {
            float4 a = __ldg(x4 + (long long)e * 8 + s);
            asm volatile("red.global.add.v4.f32 [%0], {%1, %2, %3, %4};"
                         :: "l"(dst + s * 4),
                            "f"(a.x * inv), "f"(a.y * inv),
                            "f"(a.z * inv), "f"(a.w * inv)
                         : "memory");
        }
    }
}

extern "C" void kernel_launch(void* const* d_in, const int* in_sizes, int n_in,
                              void* d_out, int out_size)
{
    const float4* x4  = (const float4*)d_in[0];
    const int*    ids = (const int*)d_in[1];

    int n_he = in_sizes[1];                     // element count of vertex_ids
    int V    = (int)((long long)out_size / 32); // output is [V, 32]
    int nbuck = (V + VB - 1) >> VB_SHIFT;
    if (nbuck > NBUCK_MAX) nbuck = NBUCK_MAX;   // (bench shape: V=1M -> 977)

    // Zero bucket counts, overflow counts, overflow length.
    void* p = nullptr;
    cudaGetSymbolAddress(&p, g_bucket_cnt);
    cudaMemsetAsync(p, 0, (size_t)nbuck * sizeof(int));
    cudaGetSymbolAddress(&p, g_ovcnt);
    cudaMemsetAsync(p, 0, (size_t)V * sizeof(int));
    cudaGetSymbolAddress(&p, g_over_n);
    cudaMemsetAsync(p, 0, sizeof(int));

    // P1: coarse binning.
    p1_bin_kernel<<<(n_he + EPB - 1) / EPB, P1_THREADS>>>(ids, n_he, nbuck);

    // P2: fine sort (single bucket read, atomic-free placement; ~104 KB smem).
    size_t smem = (size_t)(2 * VB + 2 + 3 * CAP_B) * sizeof(int);
    cudaFuncSetAttribute(p2_sort_kernel,
                         cudaFuncAttributeMaxDynamicSharedMemorySize, (int)smem);
    p2_sort_kernel<<<nbuck, 1024, smem>>>(V, nbuck);

    // P3: gather + mean.
    {
        long long total = (long long)V * 8;
        int threads = 256;
        int blocks = (int)((total + threads - 1) / threads);
        gather_kernel<<<blocks, threads>>>(x4, (float4*)d_out, V);
    }

    // P4: exact overflow fixup (tiny; normally exits immediately).
    fixup_kernel<<<32, 256>>>(x4, (float*)d_out);
}